// round 14
// baseline (speedup 1.0000x reference)
#include <cuda_runtime.h>
#include <cuda_fp16.h>
#include <math.h>
#include <stdint.h>

#define HID    768
#define INTER  3072
#define NHEAD  12
#define DH     64
#define NTOK   16384
#define WWIN   256
#define K1     HID
#define KC2    (HID + INTER)
#define K2     KC2
#define QKVC   (3 * HID)     // 2304 fp16 qkv cols

__device__ __align__(256) float   g_xn   [(size_t)NTOK * HID];
__device__ __align__(256) __half  g_qkvh [(size_t)NTOK * QKVC];   // q(prescaled)|k|v fp16
__device__ __align__(256) __half  g_am1  [(size_t)NTOK * K1];
__device__ __align__(256) __half  g_am2  [(size_t)NTOK * K2];
__device__ __align__(256) __half  g_bm1  [(size_t)(3*HID+INTER) * K1];
__device__ __align__(256) __half  g_bm2  [(size_t)HID * K2];

__device__ __forceinline__ uint32_t smem_u32(const void* p) {
    uint32_t a;
    asm("{ .reg .u64 t; cvta.to.shared.u64 t, %1; cvt.u32.u64 %0, t; }" : "=r"(a) : "l"(p));
    return a;
}
#define CPASYNC16(sa, gp) \
    asm volatile("cp.async.cg.shared.global [%0], [%1], 16;" :: "r"(sa), "l"(gp))
#define CPASYNC16Z(sa, gp) \
    asm volatile("cp.async.cg.shared.global [%0], [%1], 16, 0;" :: "r"(sa), "l"(gp))
#define CP_COMMIT() asm volatile("cp.async.commit_group;" ::: "memory")
#define CP_WAIT1()  asm volatile("cp.async.wait_group 1;" ::: "memory")
#define CP_WAIT0()  asm volatile("cp.async.wait_group 0;" ::: "memory")
#define LDSM4(r0, r1, r2, r3, ad) \
    asm volatile("ldmatrix.sync.aligned.m8n8.x4.shared.b16 {%0,%1,%2,%3}, [%4];" \
                 : "=r"(r0), "=r"(r1), "=r"(r2), "=r"(r3) : "r"(ad))
#define LDSM4T(r0, r1, r2, r3, ad) \
    asm volatile("ldmatrix.sync.aligned.m8n8.x4.trans.shared.b16 {%0,%1,%2,%3}, [%4];" \
                 : "=r"(r0), "=r"(r1), "=r"(r2), "=r"(r3) : "r"(ad))
#define MMA16816(d, a, b0, b1) \
    asm volatile("mma.sync.aligned.m16n8k16.row.col.f32.f16.f16.f32 " \
                 "{%0,%1,%2,%3}, {%4,%5,%6,%7}, {%8,%9}, {%0,%1,%2,%3};" \
                 : "+f"((d)[0]), "+f"((d)[1]), "+f"((d)[2]), "+f"((d)[3]) \
                 : "r"((a)[0]), "r"((a)[1]), "r"((a)[2]), "r"((a)[3]), "r"(b0), "r"(b1))

__device__ __forceinline__ uint32_t h2pack(float x, float y) {
    __half2 t = __floats2half2_rn(x, y);
    return *(uint32_t*)&t;
}

// ---------------- LayerNorm + fp16 A emit ----------------
__global__ void ln_kernel(const float* __restrict__ x,
                          const float* __restrict__ gamma,
                          const float* __restrict__ beta) {
    const int row = blockIdx.x, t = threadIdx.x;
    const float* xr = x + (size_t)row * HID;
    float v0 = xr[t], v1 = xr[t + 256], v2 = xr[t + 512];
    float s  = v0 + v1 + v2;
    float ss = v0 * v0 + v1 * v1 + v2 * v2;
    #pragma unroll
    for (int o = 16; o; o >>= 1) {
        s  += __shfl_xor_sync(0xffffffffu, s,  o);
        ss += __shfl_xor_sync(0xffffffffu, ss, o);
    }
    __shared__ float sh[18];
    if ((t & 31) == 0) { sh[t >> 5] = s; sh[(t >> 5) + 8] = ss; }
    __syncthreads();
    if (t == 0) {
        float S = 0.f, SS = 0.f;
        #pragma unroll
        for (int i = 0; i < 8; i++) { S += sh[i]; SS += sh[i + 8]; }
        float mu  = S * (1.0f / HID);
        float var = SS * (1.0f / HID) - mu * mu;
        sh[16] = mu;
        sh[17] = rsqrtf(var + 1e-5f);
    }
    __syncthreads();
    const float mu = sh[16], rs = sh[17];
    float* o = g_xn + (size_t)row * HID;
    __half* a1 = g_am1 + (size_t)row * K1;
    #pragma unroll
    for (int g = 0; g < 3; g++) {
        const int c = t + g * 256;
        const float v = (g == 0 ? v0 : (g == 1 ? v1 : v2));
        const float y = (v - mu) * rs * gamma[c] + beta[c];
        o[c] = y;
        a1[c] = __float2half_rn(y);
    }
}

// ---------------- weight transpose to fp16 ----------------
__global__ void conv_w_kernel(const float* __restrict__ w, __half* __restrict__ bm,
                              int Kdim, int Ndim) {
    __shared__ float tile[32][33];
    const int k0 = blockIdx.y << 5, n0 = blockIdx.x << 5;
    const int tx = threadIdx.x & 31, tr = threadIdx.x >> 5;
    #pragma unroll
    for (int r = 0; r < 32; r += 8)
        tile[tr + r][tx] = w[(size_t)(k0 + tr + r) * Ndim + n0 + tx];
    __syncthreads();
    const int nl = threadIdx.x & 31;
    const int kq = threadIdx.x >> 5;
    __align__(8) __half t[4];
    #pragma unroll
    for (int j = 0; j < 4; j++)
        t[j] = __float2half_rn(tile[kq * 4 + j][nl]);
    uint2* dp = (uint2*)(bm + (size_t)(n0 + nl) * (size_t)Kdim + (size_t)(k0 + kq * 4));
    *dp = *(const uint2*)t;
}

// ---------------- GEMM: C[M,N] = A[M,K] * B[N,K]^T ----------------
// CTA 128x128, 128 threads = 4 warps, warp tile 64x64, BK=64, 3-stage cp.async.
// mode 1: qkv -> fp16 outH (RoPE on q,k; q pre-scaled 1/8) + gelu fp16 -> outT
// mode 2: outF = acc + bias + resid
__global__ __launch_bounds__(128, 2)
void gemm_mma(const __half* __restrict__ A, const __half* __restrict__ B,
              const float* __restrict__ bias, const float* __restrict__ resid,
              float* __restrict__ outF, __half* __restrict__ outH,
              __half* __restrict__ outT,
              const float* __restrict__ psin, const float* __restrict__ pcos,
              int K, int mode)
{
    extern __shared__ char sm[];
    const uint32_t sb = smem_u32(sm);
    const int tid = threadIdx.x, lane = tid & 31, wid = tid >> 5;   // 4 warps
    const int m0 = blockIdx.y << 7, n0 = blockIdx.x << 7;
    const int wm = wid & 1, wn = wid >> 1;                          // 2x2 warp grid

    auto load_stage = [&](int c, int s) {
        const int kc = c << 6;
        const __half* Ab = A + (size_t)m0 * K + kc;
        const __half* Bb = B + (size_t)n0 * K + kc;
        const uint32_t stA = sb + s * 32768;
        const uint32_t stB = stA + 16384;
        #pragma unroll
        for (int i = 0; i < 8; i++) {
            const int cid = tid + (i << 7);
            const int row = cid >> 3, ch = cid & 7;
            const uint32_t so = row * 128 + ((ch ^ (row & 7)) << 4);
            CPASYNC16(stA + so, Ab + (size_t)row * K + (ch << 3));
            CPASYNC16(stB + so, Bb + (size_t)row * K + (ch << 3));
        }
    };

    const int la = lane & 7;
    const int rowA0 = wm * 64 + la + ((lane >> 3) & 1) * 8;   // + mf*16 (mf 0..3)
    const int swA   = rowA0 & 7;
    const int cbA   = (lane >> 4) & 1;
    const int rowB0 = wn * 64 + la + ((lane >> 4) & 1) * 8;   // + nf2*16
    const int swB   = rowB0 & 7;
    const int cbB   = (lane >> 3) & 1;

    float acc[4][8][4];
    #pragma unroll
    for (int i = 0; i < 4; i++)
        #pragma unroll
        for (int j = 0; j < 8; j++)
            #pragma unroll
            for (int q = 0; q < 4; q++) acc[i][j][q] = 0.f;

    const int nc = K >> 6;
    load_stage(0, 0); CP_COMMIT();
    load_stage(1, 1); CP_COMMIT();

    for (int c = 0; c < nc; c++) {
        CP_WAIT1();
        __syncthreads();
        if (c + 2 < nc) load_stage(c + 2, (c + 2) % 3);
        CP_COMMIT();

        const uint32_t stA = sb + (c % 3) * 32768;
        const uint32_t stB = stA + 16384;
        #pragma unroll
        for (int kk = 0; kk < 4; kk++) {
            uint32_t a[4][4];
            #pragma unroll
            for (int mf = 0; mf < 4; mf++) {
                const uint32_t ad = stA + (rowA0 + mf * 16) * 128 + (((kk * 2 + cbA) ^ swA) << 4);
                LDSM4(a[mf][0], a[mf][1], a[mf][2], a[mf][3], ad);
            }
            uint32_t b[4][4];
            #pragma unroll
            for (int nf2 = 0; nf2 < 4; nf2++) {
                const uint32_t bd = stB + (rowB0 + nf2 * 16) * 128 + (((kk * 2 + cbB) ^ swB) << 4);
                LDSM4(b[nf2][0], b[nf2][1], b[nf2][2], b[nf2][3], bd);
            }
            #pragma unroll
            for (int mf = 0; mf < 4; mf++)
                #pragma unroll
                for (int nf = 0; nf < 8; nf++)
                    MMA16816(acc[mf][nf], a[mf], b[nf >> 1][(nf & 1) * 2], b[nf >> 1][(nf & 1) * 2 + 1]);
        }
        // barrier at top of next iteration separates compute from stage overwrite
    }
    __syncthreads();

    // stage C (128x128) into smem, rows padded to 132 floats
    float* smC = (float*)sm;
    #pragma unroll
    for (int mf = 0; mf < 4; mf++)
        #pragma unroll
        for (int nf = 0; nf < 8; nf++)
            #pragma unroll
            for (int q = 0; q < 4; q++) {
                const int row = wm * 64 + mf * 16 + (lane >> 2) + ((q >> 1) << 3);
                const int col = wn * 64 + nf * 8 + ((lane & 3) << 1) + (q & 1);
                smC[row * 132 + col] = acc[mf][nf][q];
            }
    __syncthreads();

    // epilogue: one row per thread, two 64-col halves
    const int r = tid;
    const int mrow = m0 + r;
    #pragma unroll 1
    for (int hb = 0; hb < 2; hb++) {
        const int nb = n0 + hb * 64;
        const float* cr = smC + r * 132 + hb * 64;

        if (mode == 1) {
            if (nb < 3 * HID) {
                float vb[64];
                #pragma unroll
                for (int i = 0; i < 64; i++) vb[i] = cr[i] + bias[nb + i];
                if (nb < 2 * HID) {   // RoPE on q,k (64-col span == one head)
                    const float* sp  = psin + (size_t)mrow * DH;
                    const float* cp2 = pcos + (size_t)mrow * DH;
                    #pragma unroll
                    for (int i = 0; i < 32; i++) {
                        const float e = vb[2*i], o = vb[2*i+1];
                        const float sn = sp[2*i], cs = cp2[2*i];
                        vb[2*i]   = e * cs - o * sn;
                        vb[2*i+1] = o * cs + e * sn;
                    }
                }
                const float sc = (nb < HID) ? 0.125f : 1.0f;   // pre-scale q
                __align__(16) __half pr[64];
                #pragma unroll
                for (int i = 0; i < 64; i++) pr[i] = __float2half_rn(vb[i] * sc);
                uint4* dp = (uint4*)(outH + (size_t)mrow * QKVC + nb);
                const uint4* ts = (const uint4*)pr;
                #pragma unroll
                for (int j = 0; j < 8; j++) dp[j] = ts[j];
            } else {
                __align__(16) __half pr[64];
                #pragma unroll
                for (int i = 0; i < 64; i++) {
                    float v = cr[i] + bias[nb + i];
                    float u = v * (0.7978845608028654f + 0.0356774081f * v * v);
                    v = 0.5f * v * (1.0f + tanhf(u));
                    pr[i] = __float2half_rn(v);
                }
                uint4* dp = (uint4*)(outT + (size_t)mrow * K2 + (nb - 2 * HID));
                const uint4* ts = (const uint4*)pr;
                #pragma unroll
                for (int j = 0; j < 8; j++) dp[j] = ts[j];
            }
        } else {
            float* dst = outF + (size_t)mrow * HID + nb;
            const float* rp = resid + (size_t)mrow * HID + nb;
            #pragma unroll
            for (int q = 0; q < 16; q++) {
                float4 rv = *(const float4*)(rp + q * 4);
                float4 ov;
                ov.x = cr[q*4+0] + bias[nb+q*4+0] + rv.x;
                ov.y = cr[q*4+1] + bias[nb+q*4+1] + rv.y;
                ov.z = cr[q*4+2] + bias[nb+q*4+2] + rv.z;
                ov.w = cr[q*4+3] + bias[nb+q*4+3] + rv.w;
                *(float4*)(dst + q * 4) = ov;
            }
        }
    }
}

// ---------------- flash attention: fp16 feed, cp.async double-buffer, ldmatrix.trans V ----------------
__global__ __launch_bounds__(256, 2)
void attn_mma(const int* __restrict__ plen) {
    __shared__ __align__(16) __half Qs[128 * 64];      // 16 KB
    __shared__ __align__(16) __half Ks[2][64 * 64];    // 16 KB
    __shared__ __align__(16) __half Vs[2][64 * 64];    // 16 KB
    const int h  = blockIdx.y;
    const int q0 = blockIdx.x << 7;
    const int tid = threadIdx.x, lane = tid & 31, wid = tid >> 5;
    const unsigned lm = ~((unsigned)(*plen) - 1u);

    const uint32_t sq  = smem_u32(Qs);
    const uint32_t sk0 = smem_u32(Ks);
    const uint32_t sv0 = smem_u32(Vs);

    #pragma unroll
    for (int i = 0; i < 4; i++) {
        const int cid = tid + (i << 8);
        const int r = cid >> 3, ch = cid & 7;
        const uint32_t so = r * 128 + ((ch ^ (r & 7)) << 4);
        CPASYNC16(sq + so, g_qkvh + (size_t)(q0 + r) * QKVC + h * DH + (ch << 3));
    }
    CP_COMMIT();

    auto loadkv = [&](int t, int b) {
        const int kbase = q0 - 256 + t * 64;
        const uint32_t skb = sk0 + b * 8192;
        const uint32_t svb = sv0 + b * 8192;
        #pragma unroll
        for (int i = 0; i < 2; i++) {
            const int cid = tid + (i << 8);
            const int r = cid >> 3, ch = cid & 7;
            const int kj = kbase + r;
            const uint32_t so = r * 128 + ((ch ^ (r & 7)) << 4);
            const __half* kp = g_qkvh + (size_t)kj * QKVC + HID + h * DH + (ch << 3);
            if (kj >= 0) {
                CPASYNC16(skb + so, kp);
                CPASYNC16(svb + so, kp + HID);
            } else {
                CPASYNC16Z(skb + so, g_qkvh);
                CPASYNC16Z(svb + so, g_qkvh);
            }
        }
    };
    loadkv(0, 0); CP_COMMIT();

    CP_WAIT1();
    __syncthreads();

    uint32_t qf[4][4];
    {
        const int rowq = wid * 16 + (lane & 7) + ((lane >> 3) & 1) * 8;
        const int sw = rowq & 7, cb = (lane >> 4) & 1;
        #pragma unroll
        for (int kk = 0; kk < 4; kk++) {
            const uint32_t ad = sq + rowq * 128 + (((kk * 2 + cb) ^ sw) << 4);
            LDSM4(qf[kk][0], qf[kk][1], qf[kk][2], qf[kk][3], ad);
        }
    }

    float m0 = -1e30f, m1 = -1e30f, l0 = 0.f, l1 = 0.f;
    float acc[8][4];
    #pragma unroll
    for (int i = 0; i < 8; i++) { acc[i][0] = acc[i][1] = acc[i][2] = acc[i][3] = 0.f; }

    const int gr = lane >> 2, gc = (lane & 3) << 1;
    const int qr0 = q0 + wid * 16 + gr;
    const unsigned sega = (unsigned)qr0 & lm;
    const unsigned segb = (unsigned)(qr0 + 8) & lm;

    const int rowk = (lane & 7) + ((lane >> 4) & 1) * 8;
    const int swk  = rowk & 7;
    const int cbk  = (lane >> 3) & 1;
    const int rvl  = lane & 15;
    const int dvs  = (lane >> 4) << 3;
    const int wq0  = q0 + wid * 16;

    for (int t = 0; t < 6; t++) {
        CP_WAIT0();
        __syncthreads();
        if (t + 1 < 6) loadkv(t + 1, (t + 1) & 1);
        CP_COMMIT();

        const uint32_t skb = sk0 + (t & 1) * 8192;
        const uint32_t svb = sv0 + (t & 1) * 8192;
        const int kbase = q0 - 256 + t * 64;
        const bool active = (wq0 + 15 >= kbase) && (wq0 - kbase - 63 <= (WWIN - 1));
        if (!active) continue;

        float s[8][4];
        #pragma unroll
        for (int i = 0; i < 8; i++) { s[i][0] = s[i][1] = s[i][2] = s[i][3] = 0.f; }
        #pragma unroll
        for (int kk = 0; kk < 4; kk++) {
            uint32_t b[4][4];
            #pragma unroll
            for (int n2 = 0; n2 < 4; n2++) {
                const uint32_t ad = skb + (rowk + n2 * 16) * 128 + (((kk * 2 + cbk) ^ swk) << 4);
                LDSM4(b[n2][0], b[n2][1], b[n2][2], b[n2][3], ad);
            }
            #pragma unroll
            for (int nf = 0; nf < 8; nf++)
                MMA16816(s[nf], qf[kk], b[nf >> 1][(nf & 1) * 2], b[nf >> 1][(nf & 1) * 2 + 1]);
        }

        float ra = -3e30f, rb = -3e30f;
        #pragma unroll
        for (int nf = 0; nf < 8; nf++) {
            const int ka = kbase + nf * 8 + gc;
            const int kb = ka + 1;
            const bool va0 = (ka >= 0) & (qr0 >= ka) & (qr0 - ka < WWIN) & (((unsigned)ka & lm) == sega);
            const bool va1 = (kb >= 0) & (qr0 >= kb) & (qr0 - kb < WWIN) & (((unsigned)kb & lm) == sega);
            const bool vb0 = (ka >= 0) & (qr0 + 8 >= ka) & (qr0 + 8 - ka < WWIN) & (((unsigned)ka & lm) == segb);
            const bool vb1 = (kb >= 0) & (qr0 + 8 >= kb) & (qr0 + 8 - kb < WWIN) & (((unsigned)kb & lm) == segb);
            s[nf][0] = va0 ? s[nf][0] : -3e30f;
            s[nf][1] = va1 ? s[nf][1] : -3e30f;
            s[nf][2] = vb0 ? s[nf][2] : -3e30f;
            s[nf][3] = vb1 ? s[nf][3] : -3e30f;
            ra = fmaxf(ra, fmaxf(s[nf][0], s[nf][1]));
            rb = fmaxf(rb, fmaxf(s[nf][2], s[nf][3]));
        }
        ra = fmaxf(ra, __shfl_xor_sync(0xffffffffu, ra, 1));
        ra = fmaxf(ra, __shfl_xor_sync(0xffffffffu, ra, 2));
        rb = fmaxf(rb, __shfl_xor_sync(0xffffffffu, rb, 1));
        rb = fmaxf(rb, __shfl_xor_sync(0xffffffffu, rb, 2));
        const float mn0 = fmaxf(m0, ra), mn1 = fmaxf(m1, rb);
        const float sf0 = __expf(m0 - mn0), sf1 = __expf(m1 - mn1);
        m0 = mn0; m1 = mn1;
        l0 *= sf0; l1 *= sf1;
        #pragma unroll
        for (int nf = 0; nf < 8; nf++) {
            acc[nf][0] *= sf0; acc[nf][1] *= sf0;
            acc[nf][2] *= sf1; acc[nf][3] *= sf1;
        }
        float rs0 = 0.f, rs1 = 0.f;
        #pragma unroll
        for (int nf = 0; nf < 8; nf++) {
            s[nf][0] = __expf(s[nf][0] - m0);
            s[nf][1] = __expf(s[nf][1] - m0);
            s[nf][2] = __expf(s[nf][2] - m1);
            s[nf][3] = __expf(s[nf][3] - m1);
            rs0 += s[nf][0] + s[nf][1];
            rs1 += s[nf][2] + s[nf][3];
        }
        rs0 += __shfl_xor_sync(0xffffffffu, rs0, 1);
        rs0 += __shfl_xor_sync(0xffffffffu, rs0, 2);
        rs1 += __shfl_xor_sync(0xffffffffu, rs1, 1);
        rs1 += __shfl_xor_sync(0xffffffffu, rs1, 2);
        l0 += rs0; l1 += rs1;

        #pragma unroll
        for (int kt = 0; kt < 4; kt++) {
            uint32_t a[4];
            a[0] = h2pack(s[2*kt][0],   s[2*kt][1]);
            a[1] = h2pack(s[2*kt][2],   s[2*kt][3]);
            a[2] = h2pack(s[2*kt+1][0], s[2*kt+1][1]);
            a[3] = h2pack(s[2*kt+1][2], s[2*kt+1][3]);
            const int rv = kt * 16 + rvl;
            #pragma unroll
            for (int n2 = 0; n2 < 4; n2++) {
                const int dv = n2 * 16 + dvs;
                const uint32_t ad = svb + rv * 128 + ((((dv >> 3)) ^ (rv & 7)) << 4);
                uint32_t b0, b1, b2, b3;
                LDSM4T(b0, b1, b2, b3, ad);
                MMA16816(acc[n2 * 2],     a, b0, b1);
                MMA16816(acc[n2 * 2 + 1], a, b2, b3);
            }
        }
    }

    const float i0 = 1.f / l0, i1 = 1.f / l1;
    __half* op0 = g_am2 + (size_t)qr0 * K2 + h * DH + gc;
    __half* op1 = op0 + (size_t)8 * K2;
    #pragma unroll
    for (int nf = 0; nf < 8; nf++) {
        uint32_t w0 = h2pack(acc[nf][0] * i0, acc[nf][1] * i0);
        uint32_t w1 = h2pack(acc[nf][2] * i1, acc[nf][3] * i1);
        *(uint32_t*)(op0 + nf * 8) = w0;
        *(uint32_t*)(op1 + nf * 8) = w1;
    }
}

// ---------------- launch ----------------
extern "C" void kernel_launch(void* const* d_in, const int* in_sizes, int n_in,
                              void* d_out, int out_size) {
    const float* x        = (const float*)d_in[0];
    const float* psin     = (const float*)d_in[2];
    const float* pcos     = (const float*)d_in[3];
    const float* ln_scale = (const float*)d_in[4];
    const float* ln_off   = (const float*)d_in[5];
    const float* w_in     = (const float*)d_in[6];
    const float* b_in     = (const float*)d_in[7];
    const float* w_out    = (const float*)d_in[8];
    const float* b_out    = (const float*)d_in[9];
    const int*   plen     = (const int*)d_in[10];
    float* out = (float*)d_out;

    float* p_xn = nullptr;
    __half *p_qkvh = nullptr, *p_am1 = nullptr, *p_am2 = nullptr, *p_bm1 = nullptr, *p_bm2 = nullptr;
    cudaGetSymbolAddress((void**)&p_xn,   g_xn);
    cudaGetSymbolAddress((void**)&p_qkvh, g_qkvh);
    cudaGetSymbolAddress((void**)&p_am1,  g_am1);
    cudaGetSymbolAddress((void**)&p_am2,  g_am2);
    cudaGetSymbolAddress((void**)&p_bm1,  g_bm1);
    cudaGetSymbolAddress((void**)&p_bm2,  g_bm2);

    static bool attr_set = false;
    const int gsmem = 3 * 32768;   // 96 KB: 3 stages; reused as 128x132 C stage
    if (!attr_set) {
        cudaFuncSetAttribute(gemm_mma, cudaFuncAttributeMaxDynamicSharedMemorySize, gsmem);
        attr_set = true;
    }

    conv_w_kernel<<<dim3((3*HID+INTER)/32, HID/32), 256>>>(w_in,  p_bm1, HID, 3*HID+INTER);
    conv_w_kernel<<<dim3(HID/32, KC2/32),           256>>>(w_out, p_bm2, KC2, HID);

    ln_kernel<<<NTOK, 256>>>(x, ln_scale, ln_off);

    // GEMM1 -> qkv fp16 (RoPE fused, q prescaled) + gelu(ff) fp16
    gemm_mma<<<dim3((3*HID+INTER)/128, NTOK/128), 128, gsmem>>>(
        p_am1, p_bm1, b_in, nullptr, nullptr, p_qkvh, p_am2, psin, pcos, K1, 1);

    attn_mma<<<dim3(NTOK/128, NHEAD), 256>>>(plen);

    // GEMM2: out = xn + [attn|gelu_ff] @ w_out + b_out
    gemm_mma<<<dim3(HID/128, NTOK/128), 128, gsmem>>>(
        p_am2, p_bm2, b_out, p_xn, out, nullptr, nullptr, nullptr, nullptr, K2, 2);
}